// round 3
// baseline (speedup 1.0000x reference)
#include <cuda_runtime.h>
#include <math.h>

// Problem constants (fixed shapes)
#define B_  8
#define N_  4096
#define C_  256
#define K_  4
#define NK_ (N_ * K_)

#define BM 128
#define BN 128
#define BK 16
#define THREADS 256
#define NTILES (N_ / BN)     // 32 col tiles
#define KBLKS  (C_ / BK)     // 16 k blocks

// Normalized features scratch (32 MB) — allocation-free rule: __device__ global.
__device__ float g_fn[(size_t)B_ * N_ * C_];

// ---------------------------------------------------------------------------
// Kernel 1: row-wise L2 normalize. One warp per row (256 floats).
// ---------------------------------------------------------------------------
__global__ void normalize_kernel(const float* __restrict__ x) {
    int row  = blockIdx.x * 8 + (threadIdx.x >> 5);
    int lane = threadIdx.x & 31;
    const float4* r = (const float4*)(x + (size_t)row * C_);
    float4 v0 = r[lane];
    float4 v1 = r[lane + 32];
    float s = v0.x * v0.x + v0.y * v0.y + v0.z * v0.z + v0.w * v0.w
            + v1.x * v1.x + v1.y * v1.y + v1.z * v1.z + v1.w * v1.w;
#pragma unroll
    for (int off = 16; off; off >>= 1)
        s += __shfl_xor_sync(0xffffffffu, s, off);
    float inv = rsqrtf(s);
    // rsqrtf has ~1e-7 rel err; refine one Newton step for fp32-exact ranking
    inv = inv * (1.5f - 0.5f * s * inv * inv);
    float4* o = (float4*)(g_fn + (size_t)row * C_);
    float4 a, b;
    a.x = v0.x * inv; a.y = v0.y * inv; a.z = v0.z * inv; a.w = v0.w * inv;
    b.x = v1.x * inv; b.y = v1.y * inv; b.z = v1.z * inv; b.w = v1.w * inv;
    o[lane]      = a;
    o[lane + 32] = b;
}

// ---------------------------------------------------------------------------
// Kernel 2: fused sim-GEMM + running top-4 + edge emit.
// CTA: 128 rows x loop over 32 col-tiles of 128 (one batch).
// 256 threads: ty = tid>>2 (0..63) owns 2 rows, tx = tid&3 owns 32 cols
// (8 float4 chunks at tx*4 + c*16). Double-buffered smem, BK=16.
// ---------------------------------------------------------------------------
__global__ __launch_bounds__(THREADS, 2)
void knn_kernel(float* __restrict__ out) {
    const int b    = blockIdx.y;
    const int row0 = blockIdx.x * BM;
    const float* __restrict__ fb = g_fn + (size_t)b * N_ * C_;

    __shared__ __align__(16) float As[2][BK][BM + 4];   // 2 x 16 x 132
    __shared__ __align__(16) float Bs[2][BK][BN + 4];

    const int tid = threadIdx.x;
    const int ty  = tid >> 2;       // 0..63 -> rows ty*2, ty*2+1
    const int tx  = tid & 3;        // 0..3  -> col chunks tx*4 + c*16

    // global-load mapping (transpose-through-registers)
    const int lm = tid >> 2;        // row/col within tile, 0..63 (+64 for it=1)
    const int lq = tid & 3;         // which float4 of the 16-wide k chunk

    float topv[2][4];
    int   topi[2][4];
#pragma unroll
    for (int i = 0; i < 2; i++)
#pragma unroll
        for (int s = 0; s < 4; s++) { topv[i][s] = -INFINITY; topi[i][s] = 0x7fffffff; }

    float4 ra[2], rb[2];

    for (int ct = 0; ct < NTILES; ct++) {
        const int col0 = ct * BN;
        float acc[2][32];
#pragma unroll
        for (int i = 0; i < 2; i++)
#pragma unroll
            for (int j = 0; j < 32; j++) acc[i][j] = 0.0f;

        // ---- prologue: stage 0 ----
#pragma unroll
        for (int it = 0; it < 2; it++) {
            int m = lm + it * 64;
            ra[it] = *(const float4*)(fb + (size_t)(row0 + m) * C_ + 4 * lq);
            rb[it] = *(const float4*)(fb + (size_t)(col0 + m) * C_ + 4 * lq);
        }
#pragma unroll
        for (int it = 0; it < 2; it++) {
            int m = lm + it * 64;
            As[0][4 * lq + 0][m] = ra[it].x; As[0][4 * lq + 1][m] = ra[it].y;
            As[0][4 * lq + 2][m] = ra[it].z; As[0][4 * lq + 3][m] = ra[it].w;
            Bs[0][4 * lq + 0][m] = rb[it].x; Bs[0][4 * lq + 1][m] = rb[it].y;
            Bs[0][4 * lq + 2][m] = rb[it].z; Bs[0][4 * lq + 3][m] = rb[it].w;
        }
        __syncthreads();

        for (int s = 0; s < KBLKS; s++) {
            const int cur = s & 1;
            // issue next stage's global loads early (latency hidden by FMAs)
            if (s < KBLKS - 1) {
                const int kk = (s + 1) * BK;
#pragma unroll
                for (int it = 0; it < 2; it++) {
                    int m = lm + it * 64;
                    ra[it] = *(const float4*)(fb + (size_t)(row0 + m) * C_ + kk + 4 * lq);
                    rb[it] = *(const float4*)(fb + (size_t)(col0 + m) * C_ + kk + 4 * lq);
                }
            }
            // compute current stage
#pragma unroll
            for (int k = 0; k < BK; k++) {
                const float2 a = *(const float2*)&As[cur][k][ty * 2];
#pragma unroll
                for (int c = 0; c < 8; c++) {
                    const float4 bv = *(const float4*)&Bs[cur][k][tx * 4 + c * 16];
                    acc[0][4 * c + 0] += a.x * bv.x;
                    acc[0][4 * c + 1] += a.x * bv.y;
                    acc[0][4 * c + 2] += a.x * bv.z;
                    acc[0][4 * c + 3] += a.x * bv.w;
                    acc[1][4 * c + 0] += a.y * bv.x;
                    acc[1][4 * c + 1] += a.y * bv.y;
                    acc[1][4 * c + 2] += a.y * bv.z;
                    acc[1][4 * c + 3] += a.y * bv.w;
                }
            }
            if (s < KBLKS - 1) {
                const int nxt = (s + 1) & 1;
#pragma unroll
                for (int it = 0; it < 2; it++) {
                    int m = lm + it * 64;
                    As[nxt][4 * lq + 0][m] = ra[it].x; As[nxt][4 * lq + 1][m] = ra[it].y;
                    As[nxt][4 * lq + 2][m] = ra[it].z; As[nxt][4 * lq + 3][m] = ra[it].w;
                    Bs[nxt][4 * lq + 0][m] = rb[it].x; Bs[nxt][4 * lq + 1][m] = rb[it].y;
                    Bs[nxt][4 * lq + 2][m] = rb[it].z; Bs[nxt][4 * lq + 3][m] = rb[it].w;
                }
            }
            __syncthreads();
        }

        // ---- fold this 2x32 block into per-lane sorted top-4 lists ----
#pragma unroll
        for (int i = 0; i < 2; i++) {
            const int g = row0 + ty * 2 + i;
#pragma unroll
            for (int c = 0; c < 8; c++) {
#pragma unroll
                for (int j = 0; j < 4; j++) {
                    int   col = col0 + tx * 4 + c * 16 + j;
                    float v   = acc[i][4 * c + j];
                    if (col != g && v > topv[i][3]) {
                        if (v > topv[i][0]) {
                            topv[i][3] = topv[i][2]; topi[i][3] = topi[i][2];
                            topv[i][2] = topv[i][1]; topi[i][2] = topi[i][1];
                            topv[i][1] = topv[i][0]; topi[i][1] = topi[i][0];
                            topv[i][0] = v;          topi[i][0] = col;
                        } else if (v > topv[i][1]) {
                            topv[i][3] = topv[i][2]; topi[i][3] = topi[i][2];
                            topv[i][2] = topv[i][1]; topi[i][2] = topi[i][1];
                            topv[i][1] = v;          topi[i][1] = col;
                        } else if (v > topv[i][2]) {
                            topv[i][3] = topv[i][2]; topi[i][3] = topi[i][2];
                            topv[i][2] = v;          topi[i][2] = col;
                        } else {
                            topv[i][3] = v;          topi[i][3] = col;
                        }
                    }
                }
            }
        }
    }

    // ---- merge the 4 tx-lanes of each ty group (shfl_xor 2,1), emit edges ----
    // Output layout (float32):
    //   [b*2*NK .. ]        : src indices
    //   [b*2*NK + NK .. ]   : tgt indices
    //   [B*2*NK + b*NK .. ] : weights
    const size_t ibase = (size_t)b * 2 * NK_;
    const size_t wbase = (size_t)B_ * 2 * NK_ + (size_t)b * NK_;
#pragma unroll
    for (int i = 0; i < 2; i++) {
        const int g = row0 + ty * 2 + i;
        int p = 0;
#pragma unroll
        for (int s = 0; s < 4; s++) {
            float cv = (p < 4) ? topv[i][p] : -INFINITY;
            int   ci = (p < 4) ? topi[i][p] : 0x7fffffff;
#pragma unroll
            for (int off = 2; off; off >>= 1) {
                float ov = __shfl_xor_sync(0xffffffffu, cv, off);
                int   oi = __shfl_xor_sync(0xffffffffu, ci, off);
                if (ov > cv || (ov == cv && oi < ci)) { cv = ov; ci = oi; }
            }
            if (p < 4 && topi[i][p] == ci) p++;   // winner lane pops its list
            if (tx == s) {
                out[ibase + (size_t)g * K_ + s]       = (float)g;
                out[ibase + NK_ + (size_t)g * K_ + s] = (float)ci;
                out[wbase + (size_t)g * K_ + s]       = cv;
            }
        }
    }
}

// ---------------------------------------------------------------------------
extern "C" void kernel_launch(void* const* d_in, const int* in_sizes, int n_in,
                              void* d_out, int out_size) {
    (void)in_sizes; (void)n_in; (void)out_size;
    const float* x = (const float*)d_in[0];
    float* out = (float*)d_out;

    normalize_kernel<<<(B_ * N_) / 8, 256>>>(x);
    dim3 grid(N_ / BM, B_);
    knn_kernel<<<grid, THREADS>>>(out);
}

// round 4
// speedup vs baseline: 1.4070x; 1.4070x over previous
#include <cuda_runtime.h>
#include <math.h>
#include <stdint.h>

// Problem constants (fixed shapes)
#define B_  8
#define N_  4096
#define C_  256
#define K_  4
#define NK_ (N_ * K_)

#define BM 128
#define BN 64
#define BK 16
#define THREADS 256
#define NTILES (N_ / BN)       // 64 col tiles
#define KSTAGES (C_ / BK)      // 16 k stages

// smem geometry: rows of BK float2 (128B) padded to 144B (18 float2) so the
// 8-row frag reads land on distinct bank groups.
#define ROW_BYTES   144
#define A_ROWS      BM
#define B_ROWS      BN
#define A_TILE_B    (A_ROWS * ROW_BYTES)            // 18432
#define STAGE_BYTES ((A_ROWS + B_ROWS) * ROW_BYTES) // 27648
#define SMEM_TOTAL  (2 * STAGE_BYTES)               // 55296

// tf32 split of normalized features: (hi, lo) per element. 64 MB scratch.
__device__ float2 g_split[(size_t)B_ * N_ * C_];

// ---------------------------------------------------------------------------
__device__ __forceinline__ float2 tf32_split(float x) {
    float hi, lo;
    asm("cvt.rna.tf32.f32 %0, %1;" : "=f"(hi) : "f"(x));
    lo = x - hi;
    asm("cvt.rna.tf32.f32 %0, %1;" : "=f"(lo) : "f"(lo));
    return make_float2(hi, lo);
}

// Kernel 1: row-wise L2 normalize + tf32 hi/lo split. One warp per row.
__global__ void normalize_kernel(const float* __restrict__ x) {
    int row  = blockIdx.x * 8 + (threadIdx.x >> 5);
    int lane = threadIdx.x & 31;
    const float4* r = (const float4*)(x + (size_t)row * C_);
    float4 v0 = r[lane];
    float4 v1 = r[lane + 32];
    float s = v0.x * v0.x + v0.y * v0.y + v0.z * v0.z + v0.w * v0.w
            + v1.x * v1.x + v1.y * v1.y + v1.z * v1.z + v1.w * v1.w;
#pragma unroll
    for (int off = 16; off; off >>= 1)
        s += __shfl_xor_sync(0xffffffffu, s, off);
    float nrm = sqrtf(s);
    float2* o = g_split + (size_t)row * C_;
    o[4 * lane + 0]       = tf32_split(v0.x / nrm);
    o[4 * lane + 1]       = tf32_split(v0.y / nrm);
    o[4 * lane + 2]       = tf32_split(v0.z / nrm);
    o[4 * lane + 3]       = tf32_split(v0.w / nrm);
    o[128 + 4 * lane + 0] = tf32_split(v1.x / nrm);
    o[128 + 4 * lane + 1] = tf32_split(v1.y / nrm);
    o[128 + 4 * lane + 2] = tf32_split(v1.z / nrm);
    o[128 + 4 * lane + 3] = tf32_split(v1.w / nrm);
}

// ---------------------------------------------------------------------------
__device__ __forceinline__ void cp16(uint32_t dst, const void* src) {
    asm volatile("cp.async.ca.shared.global [%0], [%1], 16;\n"
                 :: "r"(dst), "l"(src));
}
__device__ __forceinline__ void cp_commit() {
    asm volatile("cp.async.commit_group;\n");
}
__device__ __forceinline__ void mma_tf32(float* c, const uint32_t* a,
                                         uint32_t b0, uint32_t b1) {
    asm volatile(
        "mma.sync.aligned.m16n8k8.row.col.f32.tf32.tf32.f32 "
        "{%0,%1,%2,%3}, {%4,%5,%6,%7}, {%8,%9}, {%0,%1,%2,%3};\n"
        : "+f"(c[0]), "+f"(c[1]), "+f"(c[2]), "+f"(c[3])
        : "r"(a[0]), "r"(a[1]), "r"(a[2]), "r"(a[3]), "r"(b0), "r"(b1));
}

// ---------------------------------------------------------------------------
// Kernel 2: fused 3xTF32 tensor-core sim-GEMM + running top-4 + edge emit.
// CTA: 128 rows x (loop over 64 col-tiles of 64). 8 warps, each warp owns a
// 16x64 warp tile (m16n8k8 mma, 8 n-tiles). Double-buffered cp.async, BK=16.
// ---------------------------------------------------------------------------
__global__ __launch_bounds__(THREADS, 2)
void knn_kernel(float* __restrict__ out) {
    extern __shared__ char smem_raw[];
    const int b    = blockIdx.y;
    const int row0 = blockIdx.x * BM;
    const float2* __restrict__ fb = g_split + (size_t)b * N_ * C_;

    const int tid  = threadIdx.x;
    const int warp = tid >> 5;
    const int lane = tid & 31;
    const int gid  = lane >> 2;   // group id 0..7
    const int tq   = lane & 3;    // thread-in-group 0..3
    const int m0   = warp * 16;   // warp's row offset in the CTA tile

    const uint32_t sbase = (uint32_t)__cvta_generic_to_shared(smem_raw);

    float topv[2][4];
    int   topi[2][4];
#pragma unroll
    for (int i = 0; i < 2; i++)
#pragma unroll
        for (int s = 0; s < 4; s++) { topv[i][s] = -INFINITY; topi[i][s] = 0x7fffffff; }

    // per-thread cp.async chunk mapping (row = id>>3, 16B chunk = id&7)
    const int aid0 = tid;           // A: ids tid + i*256, i<4  (1024 chunks)
    const int bid0 = tid;           // B: ids tid + i*256, i<2  (512 chunks)

    for (int ct = 0; ct < NTILES; ct++) {
        const int col0 = ct * BN;

        float acc[32];
#pragma unroll
        for (int j = 0; j < 32; j++) acc[j] = 0.0f;

        // ---- prologue: stage 0 ----
        {
            const uint32_t sA = sbase;
            const uint32_t sB = sbase + A_TILE_B;
#pragma unroll
            for (int i = 0; i < 4; i++) {
                int id = aid0 + i * 256; int r = id >> 3, c = id & 7;
                cp16(sA + r * ROW_BYTES + c * 16,
                     fb + (size_t)(row0 + r) * C_ + c * 2);
            }
#pragma unroll
            for (int i = 0; i < 2; i++) {
                int id = bid0 + i * 256; int r = id >> 3, c = id & 7;
                cp16(sB + r * ROW_BYTES + c * 16,
                     fb + (size_t)(col0 + r) * C_ + c * 2);
            }
            cp_commit();
        }

        for (int s = 0; s < KSTAGES; s++) {
            if (s + 1 < KSTAGES) {
                const int kk = (s + 1) * BK;
                const uint32_t sA = sbase + ((s + 1) & 1) * STAGE_BYTES;
                const uint32_t sB = sA + A_TILE_B;
#pragma unroll
                for (int i = 0; i < 4; i++) {
                    int id = aid0 + i * 256; int r = id >> 3, c = id & 7;
                    cp16(sA + r * ROW_BYTES + c * 16,
                         fb + (size_t)(row0 + r) * C_ + kk + c * 2);
                }
#pragma unroll
                for (int i = 0; i < 2; i++) {
                    int id = bid0 + i * 256; int r = id >> 3, c = id & 7;
                    cp16(sB + r * ROW_BYTES + c * 16,
                         fb + (size_t)(col0 + r) * C_ + kk + c * 2);
                }
                cp_commit();
                asm volatile("cp.async.wait_group 1;\n");
            } else {
                asm volatile("cp.async.wait_group 0;\n");
            }
            __syncthreads();

            // ---- compute current stage ----
            const char* pA = smem_raw + (s & 1) * STAGE_BYTES;
            const char* pB = pA + A_TILE_B;
#pragma unroll
            for (int k8 = 0; k8 < BK; k8 += 8) {
                // A fragments (hi,lo interleaved -> one LDS.64 each)
                float2 l0 = *(const float2*)(pA + (m0 + gid)     * ROW_BYTES + (k8 + tq)     * 8);
                float2 l1 = *(const float2*)(pA + (m0 + gid + 8) * ROW_BYTES + (k8 + tq)     * 8);
                float2 l2 = *(const float2*)(pA + (m0 + gid)     * ROW_BYTES + (k8 + tq + 4) * 8);
                float2 l3 = *(const float2*)(pA + (m0 + gid + 8) * ROW_BYTES + (k8 + tq + 4) * 8);
                uint32_t ahi[4] = { __float_as_uint(l0.x), __float_as_uint(l1.x),
                                    __float_as_uint(l2.x), __float_as_uint(l3.x) };
                uint32_t alo[4] = { __float_as_uint(l0.y), __float_as_uint(l1.y),
                                    __float_as_uint(l2.y), __float_as_uint(l3.y) };
#pragma unroll
                for (int nt = 0; nt < 8; nt++) {
                    float2 p0 = *(const float2*)(pB + (nt * 8 + gid) * ROW_BYTES + (k8 + tq)     * 8);
                    float2 p1 = *(const float2*)(pB + (nt * 8 + gid) * ROW_BYTES + (k8 + tq + 4) * 8);
                    uint32_t bhi0 = __float_as_uint(p0.x), bhi1 = __float_as_uint(p1.x);
                    uint32_t blo0 = __float_as_uint(p0.y), blo1 = __float_as_uint(p1.y);
                    float* c = acc + nt * 4;
                    mma_tf32(c, ahi, bhi0, bhi1);   // hi*hi
                    mma_tf32(c, ahi, blo0, blo1);   // hi*lo
                    mma_tf32(c, alo, bhi0, bhi1);   // lo*hi
                }
            }
            __syncthreads();
        }

        // ---- fold acc into per-thread sorted top-4 lists ----
        // mma C layout: c0,c1 -> row (gid), cols 2*tq+{0,1}; c2,c3 -> row gid+8
#pragma unroll
        for (int i = 0; i < 2; i++) {
            const int g = row0 + m0 + gid + i * 8;
#pragma unroll
            for (int nt = 0; nt < 8; nt++) {
#pragma unroll
                for (int j = 0; j < 2; j++) {
                    int   col = col0 + nt * 8 + 2 * tq + j;
                    float v   = acc[nt * 4 + i * 2 + j];
                    if (col != g && v > topv[i][3]) {
                        if (v > topv[i][0]) {
                            topv[i][3] = topv[i][2]; topi[i][3] = topi[i][2];
                            topv[i][2] = topv[i][1]; topi[i][2] = topi[i][1];
                            topv[i][1] = topv[i][0]; topi[i][1] = topi[i][0];
                            topv[i][0] = v;          topi[i][0] = col;
                        } else if (v > topv[i][1]) {
                            topv[i][3] = topv[i][2]; topi[i][3] = topi[i][2];
                            topv[i][2] = topv[i][1]; topi[i][2] = topi[i][1];
                            topv[i][1] = v;          topi[i][1] = col;
                        } else if (v > topv[i][2]) {
                            topv[i][3] = topv[i][2]; topi[i][3] = topi[i][2];
                            topv[i][2] = v;          topi[i][2] = col;
                        } else {
                            topv[i][3] = v;          topi[i][3] = col;
                        }
                    }
                }
            }
        }
    }

    // ---- merge across the 4 lanes of each quad (rows shared by a quad),
    //      then emit edges. Output layout (float32):
    //   [b*2*NK .. ]        : src indices
    //   [b*2*NK + NK .. ]   : tgt indices
    //   [B*2*NK + b*NK .. ] : weights
    const size_t ibase = (size_t)b * 2 * NK_;
    const size_t wbase = (size_t)B_ * 2 * NK_ + (size_t)b * NK_;
#pragma unroll
    for (int i = 0; i < 2; i++) {
        const int g = row0 + m0 + gid + i * 8;
        int p = 0;
#pragma unroll
        for (int s = 0; s < 4; s++) {
            float cv = (p < 4) ? topv[i][p] : -INFINITY;
            int   ci = (p < 4) ? topi[i][p] : 0x7fffffff;
#pragma unroll
            for (int off = 1; off <= 2; off <<= 1) {
                float ov = __shfl_xor_sync(0xffffffffu, cv, off);
                int   oi = __shfl_xor_sync(0xffffffffu, ci, off);
                if (ov > cv || (ov == cv && oi < ci)) { cv = ov; ci = oi; }
            }
            if (p < 4 && topi[i][p] == ci) p++;   // winner lane pops its list
            if (tq == s) {
                out[ibase + (size_t)g * K_ + s]       = (float)g;
                out[ibase + NK_ + (size_t)g * K_ + s] = (float)ci;
                out[wbase + (size_t)g * K_ + s]       = cv;
            }
        }
    }
}

// ---------------------------------------------------------------------------
extern "C" void kernel_launch(void* const* d_in, const int* in_sizes, int n_in,
                              void* d_out, int out_size) {
    (void)in_sizes; (void)n_in; (void)out_size;
    const float* x = (const float*)d_in[0];
    float* out = (float*)d_out;

    cudaFuncSetAttribute(knn_kernel,
                         cudaFuncAttributeMaxDynamicSharedMemorySize, SMEM_TOTAL);

    normalize_kernel<<<(B_ * N_) / 8, 256>>>(x);
    dim3 grid(N_ / BM, B_);
    knn_kernel<<<grid, THREADS, SMEM_TOTAL>>>(out);
}

// round 7
// speedup vs baseline: 1.5507x; 1.1021x over previous
#include <cuda_runtime.h>
#include <math.h>
#include <stdint.h>

// Problem constants (fixed shapes)
#define B_  8
#define N_  4096
#define C_  256
#define K_  4
#define NK_ (N_ * K_)

#define BM 128
#define BN 64
#define BK 16
#define THREADS 256
#define NTILES  (N_ / BN)      // 64 col tiles
#define KSTAGES (C_ / BK)      // 16 k stages
#define STAGES  3

// smem rows: 16 k-values as (hi,lo) float2 = 128B data, padded to 160B.
// Stride 40 words == 8 banks (mod 32): half-warp fragment reads cover all
// 16 bank-pairs exactly -> conflict-free LDS.64 (144B stride was 2-way).
#define ROW_BYTES   160
#define A_BYTES     (BM * ROW_BYTES)          // 20480
#define B_BYTES     (BN * ROW_BYTES)          // 10240
#define STAGE_BYTES (A_BYTES + B_BYTES)       // 30720
#define SMEM_TOTAL  (STAGES * STAGE_BYTES)    // 92160

// tf32 hi/lo split of normalized features (round-4 verified layout):
// element k of row r at g_split[r*C + k] = (hi, lo). 64 MB scratch.
__device__ float2 g_split[(size_t)B_ * N_ * C_];

// ---------------------------------------------------------------------------
__device__ __forceinline__ float2 tf32_split(float x) {
    float hi, lo;
    asm("cvt.rna.tf32.f32 %0, %1;" : "=f"(hi) : "f"(x));
    lo = x - hi;
    asm("cvt.rna.tf32.f32 %0, %1;" : "=f"(lo) : "f"(lo));
    return make_float2(hi, lo);
}

// Kernel 1: row-wise L2 normalize + tf32 hi/lo split. One warp per row.
__global__ void normalize_kernel(const float* __restrict__ x) {
    int row  = blockIdx.x * 8 + (threadIdx.x >> 5);
    int lane = threadIdx.x & 31;
    const float4* r = (const float4*)(x + (size_t)row * C_);
    float4 v0 = r[lane];
    float4 v1 = r[lane + 32];
    float s = v0.x * v0.x + v0.y * v0.y + v0.z * v0.z + v0.w * v0.w
            + v1.x * v1.x + v1.y * v1.y + v1.z * v1.z + v1.w * v1.w;
#pragma unroll
    for (int off = 16; off; off >>= 1)
        s += __shfl_xor_sync(0xffffffffu, s, off);
    float nrm = sqrtf(s);
    float2* o = g_split + (size_t)row * C_;
    o[4 * lane + 0]       = tf32_split(v0.x / nrm);
    o[4 * lane + 1]       = tf32_split(v0.y / nrm);
    o[4 * lane + 2]       = tf32_split(v0.z / nrm);
    o[4 * lane + 3]       = tf32_split(v0.w / nrm);
    o[128 + 4 * lane + 0] = tf32_split(v1.x / nrm);
    o[128 + 4 * lane + 1] = tf32_split(v1.y / nrm);
    o[128 + 4 * lane + 2] = tf32_split(v1.z / nrm);
    o[128 + 4 * lane + 3] = tf32_split(v1.w / nrm);
}

// ---------------------------------------------------------------------------
__device__ __forceinline__ void cp16(uint32_t dst, const void* src) {
    asm volatile("cp.async.ca.shared.global [%0], [%1], 16;\n"
                 :: "r"(dst), "l"(src));
}
__device__ __forceinline__ void cp_commit() {
    asm volatile("cp.async.commit_group;\n");
}
__device__ __forceinline__ void mma_tf32(float* c, const uint32_t* a,
                                         uint32_t b0, uint32_t b1) {
    asm volatile(
        "mma.sync.aligned.m16n8k8.row.col.f32.tf32.tf32.f32 "
        "{%0,%1,%2,%3}, {%4,%5,%6,%7}, {%8,%9}, {%0,%1,%2,%3};\n"
        : "+f"(c[0]), "+f"(c[1]), "+f"(c[2]), "+f"(c[3])
        : "r"(a[0]), "r"(a[1]), "r"(a[2]), "r"(a[3]), "r"(b0), "r"(b1));
}

// ---------------------------------------------------------------------------
// Kernel 2: fused 3xTF32 tensor-core sim-GEMM + running top-4 + edge emit.
// CTA: 128 rows x (loop over 64 col-tiles of 64). 8 warps, each warp owns a
// FULL 16x64 warp tile (2 m16 x 8 n8, m16n8k8) -> exactly ONE warp owns each
// output row (the round-5/6 ownership bug is structurally impossible).
// 3-stage cp.async pipeline, BK=16, one __syncthreads per stage.
// ---------------------------------------------------------------------------
__global__ __launch_bounds__(THREADS, 2)
void knn_kernel(float* __restrict__ out) {
    extern __shared__ char smem_raw[];
    const int b    = blockIdx.y;
    const int row0 = blockIdx.x * BM;
    const float2* __restrict__ fb = g_split + (size_t)b * N_ * C_;

    const int tid  = threadIdx.x;
    const int warp = tid >> 5;
    const int lane = tid & 31;
    const int gid  = lane >> 2;   // group id 0..7
    const int tq   = lane & 3;    // thread-in-group 0..3
    const int m0   = warp * 16;   // warp's row offset in the CTA tile

    const uint32_t sbase = (uint32_t)__cvta_generic_to_shared(smem_raw);

    float topv[2][4];
    int   topi[2][4];
#pragma unroll
    for (int i = 0; i < 2; i++)
#pragma unroll
        for (int s = 0; s < 4; s++) { topv[i][s] = -INFINITY; topi[i][s] = 0x7fffffff; }

    for (int ct = 0; ct < NTILES; ct++) {
        const int col0 = ct * BN;

        float acc[32];
#pragma unroll
        for (int j = 0; j < 32; j++) acc[j] = 0.0f;

        __syncthreads();   // all warps done reading bufs from previous tile

        // ---- stage loader: row r gets 16 k-values = 8 chunks of 16B ----
#define LOAD_STAGE(S, BUF)                                                      \
        do {                                                                    \
            const uint32_t sA = sbase + (BUF) * STAGE_BYTES;                    \
            const uint32_t sB = sA + A_BYTES;                                   \
            _Pragma("unroll")                                                   \
            for (int i = 0; i < 4; i++) {                                       \
                int id = tid + i * 256; int r = id >> 3, c = id & 7;            \
                cp16(sA + r * ROW_BYTES + c * 16,                               \
                     fb + (size_t)(row0 + r) * C_ + (S) * 16 + c * 2);          \
            }                                                                   \
            _Pragma("unroll")                                                   \
            for (int i = 0; i < 2; i++) {                                       \
                int id = tid + i * 256; int r = id >> 3, c = id & 7;            \
                cp16(sB + r * ROW_BYTES + c * 16,                               \
                     fb + (size_t)(col0 + r) * C_ + (S) * 16 + c * 2);          \
            }                                                                   \
            cp_commit();                                                        \
        } while (0)

        // prologue: stages 0 and 1
        LOAD_STAGE(0, 0);
        LOAD_STAGE(1, 1);

        for (int s = 0; s < KSTAGES; s++) {
            if (s + 1 < KSTAGES)
                asm volatile("cp.async.wait_group 1;\n");
            else
                asm volatile("cp.async.wait_group 0;\n");
            __syncthreads();

            if (s + 2 < KSTAGES)
                LOAD_STAGE(s + 2, (s + 2) % STAGES);

            // ---- compute stage s (round-4 verified fragment mapping) ----
            const char* pA = smem_raw + (s % STAGES) * STAGE_BYTES;
            const char* pB = pA + A_BYTES;
#pragma unroll
            for (int k8 = 0; k8 < BK; k8 += 8) {
                const char* abase = pA + (m0 + gid) * ROW_BYTES;
                float2 l0 = *(const float2*)(abase + (k8 + tq) * 8);
                float2 l1 = *(const float2*)(abase + 8 * ROW_BYTES + (k8 + tq) * 8);
                float2 l2 = *(const float2*)(abase + (k8 + tq + 4) * 8);
                float2 l3 = *(const float2*)(abase + 8 * ROW_BYTES + (k8 + tq + 4) * 8);
                uint32_t ahi[4] = { __float_as_uint(l0.x), __float_as_uint(l1.x),
                                    __float_as_uint(l2.x), __float_as_uint(l3.x) };
                uint32_t alo[4] = { __float_as_uint(l0.y), __float_as_uint(l1.y),
                                    __float_as_uint(l2.y), __float_as_uint(l3.y) };
#pragma unroll
                for (int nt = 0; nt < 8; nt++) {
                    const char* bb = pB + (nt * 8 + gid) * ROW_BYTES;
                    float2 p0 = *(const float2*)(bb + (k8 + tq) * 8);
                    float2 p1 = *(const float2*)(bb + (k8 + tq + 4) * 8);
                    uint32_t bhi0 = __float_as_uint(p0.x), blo0 = __float_as_uint(p0.y);
                    uint32_t bhi1 = __float_as_uint(p1.x), blo1 = __float_as_uint(p1.y);
                    float* c = acc + nt * 4;
                    mma_tf32(c, ahi, bhi0, bhi1);   // hi*hi
                    mma_tf32(c, ahi, blo0, blo1);   // hi*lo
                    mma_tf32(c, alo, bhi0, bhi1);   // lo*hi
                }
            }
        }
#undef LOAD_STAGE

        // ---- fold acc into per-thread sorted top-4 lists ----
        // mma C layout: c0,c1 -> row gid, cols 2*tq+{0,1}; c2,c3 -> row gid+8
#pragma unroll
        for (int i = 0; i < 2; i++) {
            const int g = row0 + m0 + gid + i * 8;
#pragma unroll
            for (int nt = 0; nt < 8; nt++) {
#pragma unroll
                for (int j = 0; j < 2; j++) {
                    int   col = col0 + nt * 8 + 2 * tq + j;
                    float v   = acc[nt * 4 + i * 2 + j];
                    if (col != g && v > topv[i][3]) {
                        if (v > topv[i][0]) {
                            topv[i][3] = topv[i][2]; topi[i][3] = topi[i][2];
                            topv[i][2] = topv[i][1]; topi[i][2] = topi[i][1];
                            topv[i][1] = topv[i][0]; topi[i][1] = topi[i][0];
                            topv[i][0] = v;          topi[i][0] = col;
                        } else if (v > topv[i][1]) {
                            topv[i][3] = topv[i][2]; topi[i][3] = topi[i][2];
                            topv[i][2] = topv[i][1]; topi[i][2] = topi[i][1];
                            topv[i][1] = v;          topi[i][1] = col;
                        } else if (v > topv[i][2]) {
                            topv[i][3] = topv[i][2]; topi[i][3] = topi[i][2];
                            topv[i][2] = v;          topi[i][2] = col;
                        } else {
                            topv[i][3] = v;          topi[i][3] = col;
                        }
                    }
                }
            }
        }
    }

    // ---- merge across the 4 lanes of each quad (quad shares each row),
    //      then emit edges. Output layout (float32):
    //   [b*2*NK .. ]        : src indices
    //   [b*2*NK + NK .. ]   : tgt indices
    //   [B*2*NK + b*NK .. ] : weights
    const size_t ibase = (size_t)b * 2 * NK_;
    const size_t wbase = (size_t)B_ * 2 * NK_ + (size_t)b * NK_;
#pragma unroll
    for (int i = 0; i < 2; i++) {
        const int g = row0 + m0 + gid + i * 8;
        int p = 0;
#pragma unroll
        for (int s = 0; s < 4; s++) {
            float cv = (p < 4) ? topv[i][p] : -INFINITY;
            int   ci = (p < 4) ? topi[i][p] : 0x7fffffff;
#pragma unroll
            for (int off = 1; off <= 2; off <<= 1) {
                float ov = __shfl_xor_sync(0xffffffffu, cv, off);
                int   oi = __shfl_xor_sync(0xffffffffu, ci, off);
                if (ov > cv || (ov == cv && oi < ci)) { cv = ov; ci = oi; }
            }
            if (p < 4 && topi[i][p] == ci) p++;   // winner lane pops its list
            if (tq == s) {
                out[ibase + (size_t)g * K_ + s]       = (float)g;
                out[ibase + NK_ + (size_t)g * K_ + s] = (float)ci;
                out[wbase + (size_t)g * K_ + s]       = cv;
            }
        }
    }
}

// ---------------------------------------------------------------------------
extern "C" void kernel_launch(void* const* d_in, const int* in_sizes, int n_in,
                              void* d_out, int out_size) {
    (void)in_sizes; (void)n_in; (void)out_size;
    const float* x = (const float*)d_in[0];
    float* out = (float*)d_out;

    cudaFuncSetAttribute(knn_kernel,
                         cudaFuncAttributeMaxDynamicSharedMemorySize, SMEM_TOTAL);

    normalize_kernel<<<(B_ * N_) / 8, 256>>>(x);
    dim3 grid(N_ / BM, B_);
    knn_kernel<<<grid, THREADS, SMEM_TOTAL>>>(out);
}